// round 2
// baseline (speedup 1.0000x reference)
#include <cuda_runtime.h>

// Problem shape constants (match setup_inputs)
#define NN 100000
#define EE 262144
#define BBQ 64

// ---------------- scratch (static device globals; no allocation) -------------
__device__ float    g_nodeL[(size_t)NN * 64];
__device__ float    g_nodeR[(size_t)NN * 64];
__device__ float    g_logits[EE];          // logits, then reused for ex = exp(...)
__device__ float    g_segsum[NN];
__device__ unsigned g_segmax[NN];
__device__ float    g_Acat[128 * 128];     // [d][oc]: oc<64 -> A_L, else A_R
__device__ float    g_Bcat[128 * 128];     // [d][2o]=B_L, [d][2o+1]=B_R (interleaved)
__device__ float    g_cvecA[128];          // b_proj folded node bias
__device__ float    g_qL[BBQ * 64];
__device__ float    g_qR[BBQ * 64];

// ordered-uint mapping for float atomicMax (monotonic over all finite floats)
__device__ __forceinline__ unsigned f2ord(float f) {
    unsigned u = __float_as_uint(f);
    return (u & 0x80000000u) ? ~u : (u | 0x80000000u);
}
__device__ __forceinline__ float ord2f(unsigned u) {
    return (u & 0x80000000u) ? __uint_as_float(u & 0x7fffffffu)
                             : __uint_as_float(~u);
}

// ---------------- init: zero accumulators + output ---------------------------
__global__ void k_init(float* __restrict__ out, int N) {
    int i = blockIdx.x * blockDim.x + threadIdx.x;
    if (i < N) {
        out[i]      = 0.f;
        g_segsum[i] = 0.f;
        g_segmax[i] = 0u;   // below every finite float key
    }
}

// ---------------- build combined matrices ------------------------------------
// A_L[d][o] = sum_s W_proj[s][d] * W_left[o][s]        (node-left path)
// A_R with W_right; B_* use W_*[:,64:128] (rel path).
__global__ void k_mat(const float* __restrict__ Wproj, const float* __restrict__ bproj,
                      const float* __restrict__ Wl, const float* __restrict__ Wr) {
    int d = blockIdx.x;            // 0..127
    int tid = threadIdx.x;         // 256
    int m = tid >> 6, o = tid & 63;
    float acc = 0.f;
    if (m == 0) {
        for (int s = 0; s < 64; s++) acc += Wproj[s * 128 + d] * Wl[o * 320 + s];
        g_Acat[d * 128 + o] = acc;
    } else if (m == 1) {
        for (int s = 0; s < 64; s++) acc += Wproj[s * 128 + d] * Wr[o * 320 + s];
        g_Acat[d * 128 + 64 + o] = acc;
    } else if (m == 2) {
        for (int s = 0; s < 64; s++) acc += Wproj[s * 128 + d] * Wl[o * 320 + 64 + s];
        g_Bcat[d * 128 + 2 * o] = acc;
    } else {
        for (int s = 0; s < 64; s++) acc += Wproj[s * 128 + d] * Wr[o * 320 + 64 + s];
        g_Bcat[d * 128 + 2 * o + 1] = acc;
    }
    if (d == 0) {  // fold b_proj into node bias
        if (m == 0) { float c = 0.f; for (int s = 0; s < 64; s++) c += bproj[s] * Wl[o * 320 + s]; g_cvecA[o] = c; }
        if (m == 1) { float c = 0.f; for (int s = 0; s < 64; s++) c += bproj[s] * Wr[o * 320 + s]; g_cvecA[64 + o] = c; }
    }
}

// ---------------- per-batch query bias vectors -------------------------------
__global__ void k_q(const float* __restrict__ qsrc, const float* __restrict__ qrel,
                    const float* __restrict__ qtime,
                    const float* __restrict__ Wproj, const float* __restrict__ bproj,
                    const float* __restrict__ Wst,  const float* __restrict__ bst,
                    const float* __restrict__ Wtm,  const float* __restrict__ btm,
                    const float* __restrict__ Wl,   const float* __restrict__ bl,
                    const float* __restrict__ Wr,   const float* __restrict__ br) {
    __shared__ float qc[192];
    int b = blockIdx.x, o = threadIdx.x;  // 64 threads
    float s0 = bst[o], s1 = bproj[o], s2 = btm[o];
    for (int d = 0; d < 128; d++) {
        float xs = qsrc[b * 128 + d], xr = qrel[b * 128 + d], xt = qtime[b * 128 + d];
        s0 += xs * Wst[o * 128 + d];
        s1 += xr * Wproj[o * 128 + d];
        s2 += xt * Wtm[o * 128 + d];
    }
    qc[o] = s0; qc[64 + o] = s1; qc[128 + o] = s2;
    __syncthreads();
    float ql = bl[o], qr = br[o];
    for (int s = 0; s < 64; s++) {   // rel-path b_proj bias folded here
        ql += bproj[s] * Wl[o * 320 + 64 + s];
        qr += bproj[s] * Wr[o * 320 + 64 + s];
    }
    for (int c = 0; c < 192; c++) {
        float q = qc[c];
        ql += q * Wl[o * 320 + 128 + c];
        qr += q * Wr[o * 320 + 128 + c];
    }
    g_qL[b * 64 + o] = ql;
    g_qR[b * 64 + o] = qr;
}

// ---------------- node tables: nodeL/nodeR = m @ Acat ------------------------
// 64 nodes/block, 256 threads = 128 cols x 2 slots x 32 nodes, d chunked by 32.
__global__ void k_node(const float* __restrict__ mem, int N) {
    __shared__ float sA[32 * 128];
    __shared__ float sM[64 * 32];
    int tid = threadIdx.x;
    int oc = tid & 127, slot = tid >> 7;
    int base = blockIdx.x * 64;
    float acc[32];
#pragma unroll
    for (int n = 0; n < 32; n++) acc[n] = 0.f;
    for (int ch = 0; ch < 4; ch++) {
        const float4* A4 = (const float4*)(g_Acat + ch * 4096);
        float4* sA4 = (float4*)sA;
        for (int i = tid; i < 1024; i += 256) sA4[i] = A4[i];
        for (int i = tid; i < 512; i += 256) {
            int nl = i >> 3, c4 = (i & 7) << 2;
            int node = base + nl;
            float4 v = make_float4(0.f, 0.f, 0.f, 0.f);
            if (node < N) v = *(const float4*)(mem + (size_t)node * 128 + ch * 32 + c4);
            *(float4*)(sM + nl * 32 + c4) = v;
        }
        __syncthreads();
        for (int dd = 0; dd < 32; dd += 4) {
            float a0 = sA[(dd + 0) * 128 + oc];
            float a1 = sA[(dd + 1) * 128 + oc];
            float a2 = sA[(dd + 2) * 128 + oc];
            float a3 = sA[(dd + 3) * 128 + oc];
#pragma unroll
            for (int n = 0; n < 32; n++) {
                float4 m4 = *(const float4*)(sM + (slot * 32 + n) * 32 + dd);
                acc[n] += m4.x * a0 + m4.y * a1 + m4.z * a2 + m4.w * a3;
            }
        }
        __syncthreads();
    }
    float bias = g_cvecA[oc];
    float* dst = (oc < 64) ? (g_nodeL + oc) : (g_nodeR + (oc - 64));
#pragma unroll
    for (int n = 0; n < 32; n++) {
        int node = base + slot * 32 + n;
        if (node < N) dst[(size_t)node * 64] = acc[n] + bias;
    }
}

// ---------------- main edge kernel: logits + segment max ---------------------
// 64 edges/block, 256 threads = 64 cols x 4 slots x 16 edges.
__global__ void k_edge(const int* __restrict__ edges, const float* __restrict__ relemb,
                       const float* __restrict__ Wc, const float* __restrict__ bcen,
                       int E) {
    __shared__ float sB[4096];     // Bcat chunk (32x128), later W_center^T (64x64)
    __shared__ float sRel[2048];   // 64 edges x 32 d
    __shared__ float sRR[1024];    // 16 (slot,k) x 64
    __shared__ float sLogit[16];
    __shared__ int sI[64], sJ[64], sG[64];
    int tid = threadIdx.x;
    int o = tid & 63, slot = tid >> 6;
    int lane = tid & 31;
    int eBase = blockIdx.x * 64;

    if (tid < 64) {
        int e = eBase + tid; if (e >= E) e = E - 1;
        sI[tid] = edges[(size_t)e * 8 + 6];
        sJ[tid] = edges[(size_t)e * 8 + 7];
        sG[tid] = edges[(size_t)e * 8 + 0];
    }

    float accL[16], accR[16];
#pragma unroll
    for (int k = 0; k < 16; k++) { accL[k] = 0.f; accR[k] = 0.f; }

    for (int ch = 0; ch < 4; ch++) {
        float4* sB4 = (float4*)sB;
        const float4* B4 = (const float4*)(g_Bcat + ch * 4096);
        for (int i = tid; i < 1024; i += 256) sB4[i] = B4[i];
        for (int i = tid; i < 512; i += 256) {
            int el = i >> 3, c4 = (i & 7) << 2;
            int e = eBase + el; if (e >= E) e = E - 1;
            *(float4*)(sRel + el * 32 + c4) =
                *(const float4*)(relemb + (size_t)e * 128 + ch * 32 + c4);
        }
        __syncthreads();
        for (int dd = 0; dd < 32; dd += 4) {
            float2 b0 = *(float2*)(sB + (dd + 0) * 128 + 2 * o);
            float2 b1 = *(float2*)(sB + (dd + 1) * 128 + 2 * o);
            float2 b2 = *(float2*)(sB + (dd + 2) * 128 + 2 * o);
            float2 b3 = *(float2*)(sB + (dd + 3) * 128 + 2 * o);
#pragma unroll
            for (int k = 0; k < 16; k++) {
                float4 r = *(const float4*)(sRel + (slot * 16 + k) * 32 + dd);
                accL[k] += r.x * b0.x + r.y * b1.x + r.z * b2.x + r.w * b3.x;
                accR[k] += r.x * b0.y + r.y * b1.y + r.z * b2.y + r.w * b3.y;
            }
        }
        __syncthreads();
    }

    // stage W_center transposed: sB[s*64 + o] = Wc[o][s]
    for (int i = tid; i < 4096; i += 256) {
        int s = i >> 6, oo = i & 63;
        sB[i] = Wc[oo * 64 + s];
    }
    __syncthreads();
    float bc = bcen[o];

    for (int g = 0; g < 4; g++) {
        float lv[4];
#pragma unroll
        for (int k = 0; k < 4; k++) {
            int e16 = g * 4 + k;
            int idx = slot * 16 + e16;
            int ii = sI[idx], jj = sJ[idx], bb = sG[idx];
            float lp = accL[e16] + g_nodeL[(size_t)ii * 64 + o] + g_qL[bb * 64 + o];
            float rp = accR[e16] + g_nodeR[(size_t)jj * 64 + o] + g_qR[bb * 64 + o];
            lv[k] = (lp >= 0.f) ? lp : 0.01f * lp;
            float rr = (rp >= 0.f) ? rp : 0.01f * rp;
            sRR[(slot * 4 + k) * 64 + o] = rr;
        }
        if (tid < 16) sLogit[tid] = 0.f;
        __syncthreads();

        float racc[4] = {0.f, 0.f, 0.f, 0.f};
        for (int s = 0; s < 64; s += 4) {
            float w0 = sB[(s + 0) * 64 + o];
            float w1 = sB[(s + 1) * 64 + o];
            float w2 = sB[(s + 2) * 64 + o];
            float w3 = sB[(s + 3) * 64 + o];
#pragma unroll
            for (int k = 0; k < 4; k++) {
                float4 rv = *(const float4*)(sRR + (slot * 4 + k) * 64 + s);
                racc[k] += rv.x * w0 + rv.y * w1 + rv.z * w2 + rv.w * w3;
            }
        }
#pragma unroll
        for (int k = 0; k < 4; k++) {
            float p = lv[k] * (racc[k] + bc);
#pragma unroll
            for (int off = 16; off; off >>= 1)
                p += __shfl_down_sync(0xffffffffu, p, off);
            if (lane == 0) atomicAdd(&sLogit[slot * 4 + k], p);
        }
        __syncthreads();
        if (tid < 16) {
            int sl = tid >> 2, k = tid & 3;
            int e16 = g * 4 + k;
            int e = eBase + sl * 16 + e16;
            if (e < E) {
                float lg = sLogit[tid];
                g_logits[e] = lg;
                atomicMax(&g_segmax[sI[sl * 16 + e16]], f2ord(lg));
            }
        }
        __syncthreads();
    }
}

// ---------------- exp + segment sum ------------------------------------------
__global__ void k_exp(const int* __restrict__ edges, int E) {
    int e = blockIdx.x * blockDim.x + threadIdx.x;
    if (e < E) {
        int i = edges[(size_t)e * 8 + 6];
        float mx = ord2f(g_segmax[i]);
        float ex = expf(g_logits[e] - mx);
        g_logits[e] = ex;                    // reuse buffer for ex
        atomicAdd(&g_segsum[i], ex);
    }
}

// ---------------- per-batch top-k + scatter-add ------------------------------
// One block per batch. Bitonic sort 4096 (value desc, index asc for ties).
__global__ void k_topk(const int* __restrict__ edges, const float* __restrict__ natt,
                       const int* __restrict__ maxe, float* __restrict__ out, int E_per) {
    __shared__ float sV[4096];
    __shared__ int   sId[4096];
    int tid = threadIdx.x;
    int b = blockIdx.x;
    for (int t = tid; t < 4096; t += 1024) {
        float val = -1.f;
        if (t < E_per) {
            int e = b * E_per + t;
            int i = edges[(size_t)e * 8 + 6];
            float sm = g_logits[e] / g_segsum[i];
            val = sm * natt[i];             // target_att >= 0
        }
        sV[t] = val; sId[t] = t;
    }
    __syncthreads();
    for (int k = 2; k <= 4096; k <<= 1) {
        for (int j = k >> 1; j > 0; j >>= 1) {
            for (int t = tid; t < 4096; t += 1024) {
                int ixj = t ^ j;
                if (ixj > t) {
                    bool up = ((t & k) == 0);
                    float va = sV[t], vb = sV[ixj];
                    int ia = sId[t], ib = sId[ixj];
                    bool aLess = (va < vb) || (va == vb && ia > ib);
                    if (aLess == up) {
                        sV[t] = vb; sV[ixj] = va;
                        sId[t] = ib; sId[ixj] = ia;
                    }
                }
            }
            __syncthreads();
        }
    }
    int kk = maxe[0];
    if (kk > E_per) kk = E_per;
    for (int r = tid; r < kk; r += 1024) {
        int t = sId[r];
        int e = b * E_per + t;
        int i = edges[(size_t)e * 8 + 6];
        int j = edges[(size_t)e * 8 + 7];
        float sm = g_logits[e] / g_segsum[i];
        atomicAdd(&out[j], sm * sV[r]);     // pruned_sm * pruned_att
    }
}

// ---------------- launcher ---------------------------------------------------
extern "C" void kernel_launch(void* const* d_in, const int* in_sizes, int n_in,
                              void* d_out, int out_size) {
    const int*   edges = (const int*)d_in[0];
    const float* natt  = (const float*)d_in[1];
    const float* mem   = (const float*)d_in[2];
    const float* rel   = (const float*)d_in[3];
    const float* qsrc  = (const float*)d_in[4];
    const float* qrel  = (const float*)d_in[5];
    const float* qtime = (const float*)d_in[6];
    const float* Wproj = (const float*)d_in[7];
    const float* bproj = (const float*)d_in[8];
    const float* Wst   = (const float*)d_in[9];
    const float* bst   = (const float*)d_in[10];
    const float* Wtm   = (const float*)d_in[11];
    const float* btm   = (const float*)d_in[12];
    const float* Wl    = (const float*)d_in[13];
    const float* bl    = (const float*)d_in[14];
    const float* Wr    = (const float*)d_in[15];
    const float* br    = (const float*)d_in[16];
    const float* Wc    = (const float*)d_in[17];
    const float* bc    = (const float*)d_in[18];
    const int*   maxe  = (const int*)d_in[19];
    float* out = (float*)d_out;

    int E = in_sizes[0] / 8;
    int N = in_sizes[1];
    int B = in_sizes[4] / 128;
    int E_per = E / B;

    k_init<<<(N + 255) / 256, 256>>>(out, N);
    k_mat<<<128, 256>>>(Wproj, bproj, Wl, Wr);
    k_q<<<B, 64>>>(qsrc, qrel, qtime, Wproj, bproj, Wst, bst, Wtm, btm, Wl, bl, Wr, br);
    k_node<<<(N + 63) / 64, 256>>>(mem, N);
    k_edge<<<(E + 63) / 64, 256>>>(edges, rel, Wc, bc, E);
    k_exp<<<(E + 255) / 256, 256>>>(edges, E);
    k_topk<<<B, 1024>>>(edges, natt, maxe, out, E_per);
}

// round 4
// speedup vs baseline: 1.4818x; 1.4818x over previous
#include <cuda_runtime.h>
#include <cuda_bf16.h>
#include <cstdint>

#define NN 100000
#define EE 262144
#define BBQ 64

// ---------------- scratch (static device globals; no allocation) -------------
__device__ float    g_node[(size_t)NN * 128];    // [n][0..63]=L, [64..127]=R
__device__ float    g_accE[(size_t)EE * 128];    // rel@BcatT output
__device__ float    g_logits[EE];
__device__ float    g_segsum[NN];
__device__ unsigned g_segmax[NN];
__device__ float    g_cvec[128];                 // b_proj folded node bias
__device__ float    g_qL[BBQ * 64];
__device__ float    g_qR[BBQ * 64];
// combined weights, bf16 hi/lo, row-major [n][k] (n = output col, k = 0..127)
__device__ __align__(16) __nv_bfloat16 g_WA_hi[128 * 128];
__device__ __align__(16) __nv_bfloat16 g_WA_lo[128 * 128];
__device__ __align__(16) __nv_bfloat16 g_WB_hi[128 * 128];
__device__ __align__(16) __nv_bfloat16 g_WB_lo[128 * 128];

// ordered-uint mapping for float atomicMax
__device__ __forceinline__ unsigned f2ord(float f) {
    unsigned u = __float_as_uint(f);
    return (u & 0x80000000u) ? ~u : (u | 0x80000000u);
}
__device__ __forceinline__ float ord2f(unsigned u) {
    return (u & 0x80000000u) ? __uint_as_float(u & 0x7fffffffu) : __uint_as_float(~u);
}

// ---------------- init -------------------------------------------------------
__global__ void k_init(float* __restrict__ out, int N) {
    int i = blockIdx.x * blockDim.x + threadIdx.x;
    if (i < N) {
        out[i]      = 0.f;
        g_segsum[i] = 0.f;
        g_segmax[i] = 0u;
    }
}

// ---------------- build combined weight matrices (bf16 hi/lo) ----------------
// WA[n][d] = sum_s Wproj[s][d] * W(l/r)[n][s]       (node path, n<64 -> left)
// WB[n][d] = sum_s Wproj[s][d] * W(l/r)[n][64+s]    (rel path)
__global__ void k_mat(const float* __restrict__ Wproj, const float* __restrict__ bproj,
                      const float* __restrict__ Wl, const float* __restrict__ Wr) {
    int n = blockIdx.x;   // 0..127 output col
    int d = threadIdx.x;  // 0..127 K index
    const float* W = (n < 64) ? (Wl + (size_t)n * 320) : (Wr + (size_t)(n - 64) * 320);
    float a = 0.f, b = 0.f;
    for (int s = 0; s < 64; s++) {
        float wp = Wproj[s * 128 + d];
        a += wp * W[s];
        b += wp * W[64 + s];
    }
    __nv_bfloat16 ah = __float2bfloat16_rn(a);
    __nv_bfloat16 bh = __float2bfloat16_rn(b);
    g_WA_hi[n * 128 + d] = ah;
    g_WA_lo[n * 128 + d] = __float2bfloat16_rn(a - __bfloat162float(ah));
    g_WB_hi[n * 128 + d] = bh;
    g_WB_lo[n * 128 + d] = __float2bfloat16_rn(b - __bfloat162float(bh));
    if (d == 0) {
        float c = 0.f;
        for (int s = 0; s < 64; s++) c += bproj[s] * W[s];
        g_cvec[n] = c;
    }
}

// ---------------- per-batch query bias vectors -------------------------------
__global__ void k_q(const float* __restrict__ qsrc, const float* __restrict__ qrel,
                    const float* __restrict__ qtime,
                    const float* __restrict__ Wproj, const float* __restrict__ bproj,
                    const float* __restrict__ Wst,  const float* __restrict__ bst,
                    const float* __restrict__ Wtm,  const float* __restrict__ btm,
                    const float* __restrict__ Wl,   const float* __restrict__ bl,
                    const float* __restrict__ Wr,   const float* __restrict__ br) {
    __shared__ float qc[192];
    int b = blockIdx.x, o = threadIdx.x;  // 64 threads
    float s0 = bst[o], s1 = bproj[o], s2 = btm[o];
    for (int d = 0; d < 128; d++) {
        s0 += qsrc[b * 128 + d]  * Wst[o * 128 + d];
        s1 += qrel[b * 128 + d]  * Wproj[o * 128 + d];
        s2 += qtime[b * 128 + d] * Wtm[o * 128 + d];
    }
    qc[o] = s0; qc[64 + o] = s1; qc[128 + o] = s2;
    __syncthreads();
    float ql = bl[o], qr = br[o];
    for (int s = 0; s < 64; s++) {  // rel-path b_proj bias folded here
        ql += bproj[s] * Wl[o * 320 + 64 + s];
        qr += bproj[s] * Wr[o * 320 + 64 + s];
    }
    for (int c = 0; c < 192; c++) {
        float q = qc[c];
        ql += q * Wl[o * 320 + 128 + c];
        qr += q * Wr[o * 320 + 128 + c];
    }
    g_qL[b * 64 + o] = ql;
    g_qR[b * 64 + o] = qr;
}

// ---------------- mma.sync bf16 GEMM: out[M x 128] = A[M x 128] @ W^T --------
// A fp32 converted on the fly to bf16 hi/lo; 3-term split (Ah*Bh + Ah*Bl + Al*Bh).
// W given as bf16 hi/lo row-major [n][k]. Tile 128x128x128, 8 warps (2Mx4N).
#define SPITCH 136   // smem row stride in elements (conflict-free, 16B-aligned)

__device__ __forceinline__ void mma_bf16(float* c, const uint32_t* a, const uint32_t* b) {
    asm volatile(
        "mma.sync.aligned.m16n8k16.row.col.f32.bf16.bf16.f32 "
        "{%0,%1,%2,%3}, {%4,%5,%6,%7}, {%8,%9}, {%0,%1,%2,%3};"
        : "+f"(c[0]), "+f"(c[1]), "+f"(c[2]), "+f"(c[3])
        : "r"(a[0]), "r"(a[1]), "r"(a[2]), "r"(a[3]), "r"(b[0]), "r"(b[1]));
}

#define GEMM_SMEM (4 * 128 * SPITCH * 2)

__global__ void __launch_bounds__(256, 1) k_gemm(
    const float* __restrict__ A, int M,
    const __nv_bfloat16* __restrict__ Whi, const __nv_bfloat16* __restrict__ Wlo,
    const float* __restrict__ bias, float* __restrict__ out)
{
    extern __shared__ __align__(16) unsigned char smem[];
    __nv_bfloat16* sAh = (__nv_bfloat16*)smem;
    __nv_bfloat16* sAl = sAh + 128 * SPITCH;
    __nv_bfloat16* sBh = sAl + 128 * SPITCH;
    __nv_bfloat16* sBl = sBh + 128 * SPITCH;
    int tid = threadIdx.x;

    // stage weights (already bf16): 128 rows x 128 cols, 8 elems per iter
    for (int idx = tid; idx < 2048; idx += 256) {
        int row = idx >> 4, c8 = (idx & 15) << 3;
        *(float4*)(sBh + row * SPITCH + c8) = *(const float4*)(Whi + row * 128 + c8);
        *(float4*)(sBl + row * SPITCH + c8) = *(const float4*)(Wlo + row * 128 + c8);
    }

    // load + convert A: 2 threads per row, 64 cols each
    {
        int r = tid >> 1, half = tid & 1;
        long grow = (long)blockIdx.x * 128 + r;
        bool valid = grow < M;
        const float4* src = (const float4*)(A + grow * 128 + half * 64);
        int cbase = half * 64;
#pragma unroll
        for (int q = 0; q < 16; q++) {
            float4 v = valid ? src[q] : make_float4(0.f, 0.f, 0.f, 0.f);
            float xs[4] = {v.x, v.y, v.z, v.w};
#pragma unroll
            for (int p = 0; p < 2; p++) {
                float x0 = xs[2 * p], x1 = xs[2 * p + 1];
                __nv_bfloat16 h0 = __float2bfloat16_rn(x0);
                __nv_bfloat16 h1 = __float2bfloat16_rn(x1);
                __nv_bfloat16 l0 = __float2bfloat16_rn(x0 - __bfloat162float(h0));
                __nv_bfloat16 l1 = __float2bfloat16_rn(x1 - __bfloat162float(h1));
                int c = cbase + q * 4 + 2 * p;
                *(uint32_t*)(sAh + r * SPITCH + c) =
                    (uint32_t)__bfloat16_as_ushort(h0) | ((uint32_t)__bfloat16_as_ushort(h1) << 16);
                *(uint32_t*)(sAl + r * SPITCH + c) =
                    (uint32_t)__bfloat16_as_ushort(l0) | ((uint32_t)__bfloat16_as_ushort(l1) << 16);
            }
        }
    }
    __syncthreads();

    int wid = tid >> 5, lane = tid & 31;
    int wm = (wid >> 2) * 64, wn = (wid & 3) * 32;
    int g = lane >> 2, tg = lane & 3;

    float acc[4][4][4];
#pragma unroll
    for (int mi = 0; mi < 4; mi++)
#pragma unroll
        for (int ni = 0; ni < 4; ni++)
#pragma unroll
            for (int q = 0; q < 4; q++) acc[mi][ni][q] = 0.f;

#pragma unroll
    for (int ks = 0; ks < 8; ks++) {
        int kb = ks * 16;
        uint32_t ah[4][4], al[4][4];
#pragma unroll
        for (int mi = 0; mi < 4; mi++) {
            int r0 = wm + mi * 16 + g, r1 = r0 + 8;
            int c0 = kb + tg * 2, c1 = c0 + 8;
            ah[mi][0] = *(const uint32_t*)(sAh + r0 * SPITCH + c0);
            ah[mi][1] = *(const uint32_t*)(sAh + r1 * SPITCH + c0);
            ah[mi][2] = *(const uint32_t*)(sAh + r0 * SPITCH + c1);
            ah[mi][3] = *(const uint32_t*)(sAh + r1 * SPITCH + c1);
            al[mi][0] = *(const uint32_t*)(sAl + r0 * SPITCH + c0);
            al[mi][1] = *(const uint32_t*)(sAl + r1 * SPITCH + c0);
            al[mi][2] = *(const uint32_t*)(sAl + r0 * SPITCH + c1);
            al[mi][3] = *(const uint32_t*)(sAl + r1 * SPITCH + c1);
        }
        uint32_t bh[4][2], bl[4][2];
#pragma unroll
        for (int ni = 0; ni < 4; ni++) {
            int n = wn + ni * 8 + g;
            int c0 = kb + tg * 2;
            bh[ni][0] = *(const uint32_t*)(sBh + n * SPITCH + c0);
            bh[ni][1] = *(const uint32_t*)(sBh + n * SPITCH + c0 + 8);
            bl[ni][0] = *(const uint32_t*)(sBl + n * SPITCH + c0);
            bl[ni][1] = *(const uint32_t*)(sBl + n * SPITCH + c0 + 8);
        }
#pragma unroll
        for (int mi = 0; mi < 4; mi++)
#pragma unroll
            for (int ni = 0; ni < 4; ni++) {
                mma_bf16(acc[mi][ni], ah[mi], bh[ni]);
                mma_bf16(acc[mi][ni], ah[mi], bl[ni]);
                mma_bf16(acc[mi][ni], al[mi], bh[ni]);
            }
    }

    // epilogue
#pragma unroll
    for (int mi = 0; mi < 4; mi++) {
        long r0 = (long)blockIdx.x * 128 + wm + mi * 16 + g;
        long r1 = r0 + 8;
#pragma unroll
        for (int ni = 0; ni < 4; ni++) {
            int col = wn + ni * 8 + tg * 2;
            float b0 = bias ? bias[col] : 0.f;
            float b1 = bias ? bias[col + 1] : 0.f;
            if (r0 < M) {
                float2 v = make_float2(acc[mi][ni][0] + b0, acc[mi][ni][1] + b1);
                *(float2*)(out + r0 * 128 + col) = v;
            }
            if (r1 < M) {
                float2 v = make_float2(acc[mi][ni][2] + b0, acc[mi][ni][3] + b1);
                *(float2*)(out + r1 * 128 + col) = v;
            }
        }
    }
}

// ---------------- edge epilogue: leaky + center matvec + dot + segmax --------
// 64 edges/block, 256 threads = 64 cols x 4 slots x 16 edges.
__global__ void k_edge_epi(const int* __restrict__ edges,
                           const float* __restrict__ Wc, const float* __restrict__ bcen,
                           int E) {
    __shared__ float sW[4096];     // W_center^T staged [s][o]
    __shared__ float sRR[1024];
    __shared__ float sLogit[16];
    __shared__ int sI[64], sJ[64], sG[64];
    int tid = threadIdx.x;
    int o = tid & 63, slot = tid >> 6, lane = tid & 31;
    int eBase = blockIdx.x * 64;

    if (tid < 64) {
        int e = eBase + tid; if (e >= E) e = E - 1;
        sI[tid] = edges[(size_t)e * 8 + 6];
        sJ[tid] = edges[(size_t)e * 8 + 7];
        sG[tid] = edges[(size_t)e * 8 + 0];
    }
    for (int i = tid; i < 4096; i += 256) {
        int s = i >> 6, oo = i & 63;
        sW[i] = Wc[oo * 64 + s];
    }
    __syncthreads();
    float bc = bcen[o];

    for (int g = 0; g < 4; g++) {
        float lv[4];
#pragma unroll
        for (int k = 0; k < 4; k++) {
            int e16 = g * 4 + k;
            int idx = slot * 16 + e16;
            int e = eBase + idx; if (e >= E) e = E - 1;
            float accL = g_accE[(size_t)e * 128 + o];
            float accR = g_accE[(size_t)e * 128 + 64 + o];
            int ii = sI[idx], jj = sJ[idx], bb = sG[idx];
            float lp = accL + g_node[(size_t)ii * 128 + o]      + g_qL[bb * 64 + o];
            float rp = accR + g_node[(size_t)jj * 128 + 64 + o] + g_qR[bb * 64 + o];
            lv[k] = (lp >= 0.f) ? lp : 0.01f * lp;
            float rr = (rp >= 0.f) ? rp : 0.01f * rp;
            sRR[(slot * 4 + k) * 64 + o] = rr;
        }
        if (tid < 16) sLogit[tid] = 0.f;
        __syncthreads();

        float racc[4] = {0.f, 0.f, 0.f, 0.f};
        for (int s = 0; s < 64; s += 4) {
            float w0 = sW[(s + 0) * 64 + o];
            float w1 = sW[(s + 1) * 64 + o];
            float w2 = sW[(s + 2) * 64 + o];
            float w3 = sW[(s + 3) * 64 + o];
#pragma unroll
            for (int k = 0; k < 4; k++) {
                float4 rv = *(const float4*)(sRR + (slot * 4 + k) * 64 + s);
                racc[k] += rv.x * w0 + rv.y * w1 + rv.z * w2 + rv.w * w3;
            }
        }
#pragma unroll
        for (int k = 0; k < 4; k++) {
            float p = lv[k] * (racc[k] + bc);
#pragma unroll
            for (int off = 16; off; off >>= 1)
                p += __shfl_down_sync(0xffffffffu, p, off);
            if (lane == 0) atomicAdd(&sLogit[slot * 4 + k], p);
        }
        __syncthreads();
        if (tid < 16) {
            int sl = tid >> 2, k = tid & 3;
            int e16 = g * 4 + k;
            int e = eBase + sl * 16 + e16;
            if (e < E) {
                float lg = sLogit[tid];
                g_logits[e] = lg;
                atomicMax(&g_segmax[sI[sl * 16 + e16]], f2ord(lg));
            }
        }
        __syncthreads();
    }
}

// ---------------- exp + segment sum ------------------------------------------
__global__ void k_exp(const int* __restrict__ edges, int E) {
    int e = blockIdx.x * blockDim.x + threadIdx.x;
    if (e < E) {
        int i = edges[(size_t)e * 8 + 6];
        float mx = ord2f(g_segmax[i]);
        float ex = expf(g_logits[e] - mx);
        g_logits[e] = ex;
        atomicAdd(&g_segsum[i], ex);
    }
}

// ---------------- per-batch top-k + scatter-add ------------------------------
__global__ void k_topk(const int* __restrict__ edges, const float* __restrict__ natt,
                       const int* __restrict__ maxe, float* __restrict__ out, int E_per) {
    __shared__ float sV[4096];
    __shared__ int   sId[4096];
    int tid = threadIdx.x;
    int b = blockIdx.x;
    for (int t = tid; t < 4096; t += 1024) {
        float val = -1.f;
        if (t < E_per) {
            int e = b * E_per + t;
            int i = edges[(size_t)e * 8 + 6];
            float sm = g_logits[e] / g_segsum[i];
            val = sm * natt[i];
        }
        sV[t] = val; sId[t] = t;
    }
    __syncthreads();
    for (int k = 2; k <= 4096; k <<= 1) {
        for (int j = k >> 1; j > 0; j >>= 1) {
            for (int t = tid; t < 4096; t += 1024) {
                int ixj = t ^ j;
                if (ixj > t) {
                    bool up = ((t & k) == 0);
                    float va = sV[t], vb = sV[ixj];
                    int ia = sId[t], ib = sId[ixj];
                    bool aLess = (va < vb) || (va == vb && ia > ib);
                    if (aLess == up) {
                        sV[t] = vb; sV[ixj] = va;
                        sId[t] = ib; sId[ixj] = ia;
                    }
                }
            }
            __syncthreads();
        }
    }
    int kk = maxe[0];
    if (kk > E_per) kk = E_per;
    for (int r = tid; r < kk; r += 1024) {
        int t = sId[r];
        int e = b * E_per + t;
        int i = edges[(size_t)e * 8 + 6];
        int j = edges[(size_t)e * 8 + 7];
        float sm = g_logits[e] / g_segsum[i];
        atomicAdd(&out[j], sm * sV[r]);
    }
}

// ---------------- launcher ---------------------------------------------------
extern "C" void kernel_launch(void* const* d_in, const int* in_sizes, int n_in,
                              void* d_out, int out_size) {
    const int*   edges = (const int*)d_in[0];
    const float* natt  = (const float*)d_in[1];
    const float* mem   = (const float*)d_in[2];
    const float* rel   = (const float*)d_in[3];
    const float* qsrc  = (const float*)d_in[4];
    const float* qrel  = (const float*)d_in[5];
    const float* qtime = (const float*)d_in[6];
    const float* Wproj = (const float*)d_in[7];
    const float* bproj = (const float*)d_in[8];
    const float* Wst   = (const float*)d_in[9];
    const float* bst   = (const float*)d_in[10];
    const float* Wtm   = (const float*)d_in[11];
    const float* btm   = (const float*)d_in[12];
    const float* Wl    = (const float*)d_in[13];
    const float* bl    = (const float*)d_in[14];
    const float* Wr    = (const float*)d_in[15];
    const float* br    = (const float*)d_in[16];
    const float* Wc    = (const float*)d_in[17];
    const float* bc    = (const float*)d_in[18];
    const int*   maxe  = (const int*)d_in[19];
    float* out = (float*)d_out;

    int E = in_sizes[0] / 8;
    int N = in_sizes[1];
    int B = in_sizes[4] / 128;
    int E_per = E / B;

    static int smem_set = 0;
    if (!smem_set) {
        cudaFuncSetAttribute(k_gemm, cudaFuncAttributeMaxDynamicSharedMemorySize, GEMM_SMEM);
        smem_set = 1;
    }

    float *p_node, *p_accE, *p_cvec;
    __nv_bfloat16 *p_WAh, *p_WAl, *p_WBh, *p_WBl;
    cudaGetSymbolAddress((void**)&p_node, g_node);
    cudaGetSymbolAddress((void**)&p_accE, g_accE);
    cudaGetSymbolAddress((void**)&p_cvec, g_cvec);
    cudaGetSymbolAddress((void**)&p_WAh, g_WA_hi);
    cudaGetSymbolAddress((void**)&p_WAl, g_WA_lo);
    cudaGetSymbolAddress((void**)&p_WBh, g_WB_hi);
    cudaGetSymbolAddress((void**)&p_WBl, g_WB_lo);

    k_init<<<(N + 255) / 256, 256>>>(out, N);
    k_mat<<<128, 128>>>(Wproj, bproj, Wl, Wr);
    k_q<<<B, 64>>>(qsrc, qrel, qtime, Wproj, bproj, Wst, bst, Wtm, btm, Wl, bl, Wr, br);
    // node table GEMM: g_node = mem @ WA^T + cvec
    k_gemm<<<(N + 127) / 128, 256, GEMM_SMEM>>>(mem, N, p_WAh, p_WAl, p_cvec, p_node);
    // rel GEMM: g_accE = rel @ WB^T
    k_gemm<<<(E + 127) / 128, 256, GEMM_SMEM>>>(rel, E, p_WBh, p_WBl, (const float*)nullptr, p_accE);
    k_edge_epi<<<(E + 63) / 64, 256>>>(edges, Wc, bc, E);
    k_exp<<<(E + 255) / 256, 256>>>(edges, E);
    k_topk<<<B, 1024>>>(edges, natt, maxe, out, E_per);
}